// round 13
// baseline (speedup 1.0000x reference)
#include <cuda_runtime.h>
#include <cuda_fp16.h>
#include <math.h>

#define B_ 16
#define T_ 512
#define D_ 256
#define H_ 8
#define E_ 32
#define BASIS_ 8
#define HB_ 128          // H_*B_
#define HE_ 256          // H_*E_

// ---------------- scratch (static device globals; no allocation) ----------------
__device__ float   g_qw[T_*BASIS_];
__device__ float   g_kw[T_*BASIS_];
__device__ __half2 g_Qt16[T_*D_*HE_/2];    // 67MB
__device__ __half2 g_Kt16[T_*D_*HE_/2];    // 67MB
__device__ float   g_q[HB_*T_*E_];         // [h][b][t][e] fp32
__device__ float   g_k[HB_*T_*E_];
__device__ __half2 g_v16[HB_*T_*E_/2];     // [h][b][t][e] fp16
__device__ __half2 g_lamA2[T_*256];
__device__ __half2 g_oml2[T_*256];

// ---------------- K1: per-token basis mixing weights ----------------
__global__ void k1_weights(const float* __restrict__ te,
                           const float* __restrict__ Wq,
                           const float* __restrict__ Wk) {
    int t = blockIdx.x;
    int warp = threadIdx.x >> 5, lane = threadIdx.x & 31;
    const float* tr = te + t * D_;
    const float* wq = Wq + (t * BASIS_ + warp) * D_;
    const float* wk = Wk + (t * BASIS_ + warp) * D_;
    float aq = 0.f, ak = 0.f;
    #pragma unroll
    for (int m = 0; m < D_ / 32; ++m) {
        int d = lane + 32 * m;
        float x = tr[d];
        aq += x * wq[d];
        ak += x * wk[d];
    }
    #pragma unroll
    for (int o = 16; o; o >>= 1) {
        aq += __shfl_xor_sync(0xffffffffu, aq, o);
        ak += __shfl_xor_sync(0xffffffffu, ak, o);
    }
    if (lane == 0) {
        g_qw[t * BASIS_ + warp] = aq;
        g_kw[t * BASIS_ + warp] = ak;
    }
}

// ---------------- K2: Q_tilde / K_tilde build (fp16 out), t-chunked ----------------
__global__ __launch_bounds__(256) void k2_tilde(const float* __restrict__ Qb,
                                                const float* __restrict__ Kb) {
    __shared__ float sW[64 * BASIS_];
    int qk = blockIdx.y;
    int t0 = blockIdx.z << 6;
    const float* W = (qk ? g_kw : g_qw) + t0 * BASIS_;
    const float* Bs = qk ? Kb : Qb;
    uint2* Out = qk ? (uint2*)g_Kt16 : (uint2*)g_Qt16;
    for (int idx = threadIdx.x; idx < 64 * BASIS_; idx += 256) sW[idx] = W[idx];
    __syncthreads();

    int f4 = blockIdx.x * 256 + threadIdx.x;
    float4 b4[BASIS_];
    #pragma unroll
    for (int k = 0; k < BASIS_; ++k) b4[k] = ((const float4*)Bs)[k * 16384 + f4];

    for (int tt = 0; tt < 64; ++tt) {
        float4 a = make_float4(0.f, 0.f, 0.f, 0.f);
        #pragma unroll
        for (int k = 0; k < BASIS_; ++k) {
            float w = sW[tt * BASIS_ + k];
            a.x += w * b4[k].x; a.y += w * b4[k].y;
            a.z += w * b4[k].z; a.w += w * b4[k].w;
        }
        __half2 h0 = __floats2half2_rn(a.x, a.y);
        __half2 h1 = __floats2half2_rn(a.z, a.w);
        uint2 u;
        u.x = *(const unsigned int*)&h0;
        u.y = *(const unsigned int*)&h1;
        Out[(t0 + tt) * 16384 + f4] = u;
    }
}

// ---------------- K3: q/k/v projections ----------------
__global__ __launch_bounds__(256) void k3_qkv(const float* __restrict__ X,
                                              const float* __restrict__ WV) {
    __shared__ float xsT[D_][16];
    int t = blockIdx.x, m = blockIdx.y;

    for (int idx = threadIdx.x; idx < B_ * D_; idx += 256) {
        int b = idx >> 8, d = idx & 255;
        xsT[d][b] = X[((size_t)b * T_ + t) * D_ + d];
    }
    __syncthreads();

    int tc = threadIdx.x & 31;
    int tb = threadIdx.x >> 5;

    if (m < 2) {
        float acc[2][8];
        #pragma unroll
        for (int i = 0; i < 2; ++i)
            #pragma unroll
            for (int j = 0; j < 8; ++j) acc[i][j] = 0.f;
        const uint4* W = (const uint4*)((m == 0 ? g_Qt16 : g_Kt16) + (size_t)t * 32768);
        #pragma unroll 8
        for (int d = 0; d < D_; ++d) {
            float2 xv = *(const float2*)&xsT[d][tb << 1];
            uint4 wr = W[(d << 5) + tc];
            float2 w0 = __half22float2(*(const __half2*)&wr.x);
            float2 w1 = __half22float2(*(const __half2*)&wr.y);
            float2 w2 = __half22float2(*(const __half2*)&wr.z);
            float2 w3 = __half22float2(*(const __half2*)&wr.w);
            acc[0][0] += xv.x * w0.x; acc[0][1] += xv.x * w0.y;
            acc[0][2] += xv.x * w1.x; acc[0][3] += xv.x * w1.y;
            acc[0][4] += xv.x * w2.x; acc[0][5] += xv.x * w2.y;
            acc[0][6] += xv.x * w3.x; acc[0][7] += xv.x * w3.y;
            acc[1][0] += xv.y * w0.x; acc[1][1] += xv.y * w0.y;
            acc[1][2] += xv.y * w1.x; acc[1][3] += xv.y * w1.y;
            acc[1][4] += xv.y * w2.x; acc[1][5] += xv.y * w2.y;
            acc[1][6] += xv.y * w3.x; acc[1][7] += xv.y * w3.y;
        }
        float* Out = (m == 0) ? g_q : g_k;
        int e0 = tc << 3;
        int h = e0 >> 5, eo = e0 & 31;
        #pragma unroll
        for (int i = 0; i < 2; ++i) {
            int b = (tb << 1) + i;
            size_t base = (((size_t)(h * B_ + b) * T_ + t) << 5) + eo;
            *(float4*)&Out[base]     = make_float4(acc[i][0], acc[i][1], acc[i][2], acc[i][3]);
            *(float4*)&Out[base + 4] = make_float4(acc[i][4], acc[i][5], acc[i][6], acc[i][7]);
        }
    } else {
        float acc[2][4];
        #pragma unroll
        for (int i = 0; i < 2; ++i)
            #pragma unroll
            for (int j = 0; j < 4; ++j) acc[i][j] = 0.f;
        int e0 = ((m - 2) << 7) + (tc << 2);
        const float* W = WV + (size_t)t * 65536;
        #pragma unroll 8
        for (int d = 0; d < D_; ++d) {
            float2 xv = *(const float2*)&xsT[d][tb << 1];
            float4 wv = *(const float4*)&W[(d << 8) + e0];
            acc[0][0] += xv.x * wv.x; acc[0][1] += xv.x * wv.y;
            acc[0][2] += xv.x * wv.z; acc[0][3] += xv.x * wv.w;
            acc[1][0] += xv.y * wv.x; acc[1][1] += xv.y * wv.y;
            acc[1][2] += xv.y * wv.z; acc[1][3] += xv.y * wv.w;
        }
        int h = e0 >> 5, eo = e0 & 31;
        #pragma unroll
        for (int i = 0; i < 2; ++i) {
            int b = (tb << 1) + i;
            __half2 h0 = __floats2half2_rn(acc[i][0], acc[i][1]);
            __half2 h1 = __floats2half2_rn(acc[i][2], acc[i][3]);
            uint2 u;
            u.x = *(const unsigned int*)&h0;
            u.y = *(const unsigned int*)&h1;
            *(uint2*)&g_v16[(((size_t)(h * B_ + b) * T_ + t) << 4) + (eo >> 1)] = u;
        }
    }
}

// ---------------- K4: mixing coefficients (half2 out) ----------------
__global__ void k4_mix(const float* __restrict__ A, const float* __restrict__ L) {
    int t = blockIdx.x, c = threadIdx.x;
    int j0 = c << 1, j1 = j0 + 1;
    float a0 = 0.5f * (A[t * T_ + j0] + A[j0 * T_ + t]);
    float a1 = 0.5f * (A[t * T_ + j1] + A[j1 * T_ + t]);
    float lam0 = 1.0f / (1.0f + __expf(-L[t * T_ + j0]));
    float lam1 = 1.0f / (1.0f + __expf(-L[t * T_ + j1]));
    g_lamA2[t * 256 + c] = __floats2half2_rn(lam0 * a0, lam1 * a1);
    g_oml2[t * 256 + c]  = __floats2half2_rn(1.0f - lam0, 1.0f - lam1);
}

// ---------------- K57: fused scores+softmax+mix+symexp+Sinkhorn+PV ----------------
#define SM_UNION 131072
#define SM_Y     196864
#define SM_UL    200960
#define SM_MBAR  201472
#define SMEM57   201600
#define NW_      32       // warps per CTA
#define HSTEPS_  20       // 10 Sinkhorn iterations (converged ~5e-6 << fp16 noise)

#define CBAR() do { \
    asm volatile("barrier.cluster.arrive.aligned;" ::: "memory"); \
    asm volatile("barrier.cluster.wait.aligned;"  ::: "memory"); } while (0)

__global__ __launch_bounds__(1024) __cluster_dims__(4, 1, 1)
void k57(float* __restrict__ out) {
    extern __shared__ char sm[];
    __half2* tile = (__half2*)sm;                 // [128][256] half2 = M/E rows fp16
    float2*  kT2  = (float2*)(sm + SM_UNION);     // [32][257] float2 (phase 1-2)
    float*   Vs   = (float*)(sm + SM_UNION);      // [512][32] f32 (phase 5-6)
    float*   s_y  = (float*)(sm + SM_Y);          // [2][512]
    float*   s_ul = (float*)(sm + SM_UL);         // [128]

    int tid = threadIdx.x;
    int hb = blockIdx.x >> 2;
    int rank = blockIdx.x & 3;
    int warp = tid >> 5, lane = tid & 31;

    unsigned sbase;
    asm("{ .reg .u64 t; cvta.to.shared.u64 t, %1; cvt.u32.u64 %0, t; }"
        : "=r"(sbase) : "l"(sm));
    unsigned mbar = sbase + SM_MBAR;

    // init cluster mbarrier: 128 arrivals per phase (32 warps x 4 CTAs)
    if (tid == 0) {
        asm volatile("mbarrier.init.shared.b64 [%0], %1;"
                     :: "r"(mbar), "r"(128u) : "memory");
    }

    // ---- phase 1: K transpose into kT2 ----
    const float* K = g_k + hb * (T_ * E_);
    for (int idx = tid; idx < T_ * E_; idx += 1024) {
        int t = idx >> 5, e = idx & 31;
        ((float*)&kT2[e * 257 + (t >> 1)])[t & 1] = K[idx];
    }
    __syncthreads();

    // ---- phase 2: scores + softmax + mix -> tile (fp16 M, local rows) ----
    {
        const float* Q = g_q + hb * (T_ * E_);
        const float SC = 0.17677669529663687f;
        for (int p = warp; p < 64; p += NW_) {
            int i0 = p << 1, i1 = i0 + 1;
            int gi0 = (rank << 7) + i0, gi1 = gi0 + 1;
            float q0 = Q[(gi0 << 5) + lane];
            float q1 = Q[(gi1 << 5) + lane];
            float a[8][4];
            #pragma unroll
            for (int m = 0; m < 8; ++m) { a[m][0] = a[m][1] = a[m][2] = a[m][3] = 0.f; }
            #pragma unroll
            for (int d = 0; d < 32; ++d) {
                float qd0 = __shfl_sync(0xffffffffu, q0, d);
                float qd1 = __shfl_sync(0xffffffffu, q1, d);
                const float2* row = &kT2[d * 257];
                #pragma unroll
                for (int m = 0; m < 8; ++m) {
                    float2 kv = row[lane + (m << 5)];
                    a[m][0] += qd0 * kv.x; a[m][1] += qd0 * kv.y;
                    a[m][2] += qd1 * kv.x; a[m][3] += qd1 * kv.y;
                }
            }
            float mx0 = -1e30f, mx1 = -1e30f;
            #pragma unroll
            for (int m = 0; m < 8; ++m) {
                a[m][0] *= SC; a[m][1] *= SC; a[m][2] *= SC; a[m][3] *= SC;
                mx0 = fmaxf(mx0, fmaxf(a[m][0], a[m][1]));
                mx1 = fmaxf(mx1, fmaxf(a[m][2], a[m][3]));
            }
            #pragma unroll
            for (int o = 16; o; o >>= 1) {
                mx0 = fmaxf(mx0, __shfl_xor_sync(0xffffffffu, mx0, o));
                mx1 = fmaxf(mx1, __shfl_xor_sync(0xffffffffu, mx1, o));
            }
            float sm0 = 0.f, sm1 = 0.f;
            #pragma unroll
            for (int m = 0; m < 8; ++m) {
                a[m][0] = __expf(a[m][0] - mx0); a[m][1] = __expf(a[m][1] - mx0);
                a[m][2] = __expf(a[m][2] - mx1); a[m][3] = __expf(a[m][3] - mx1);
                sm0 += a[m][0] + a[m][1];
                sm1 += a[m][2] + a[m][3];
            }
            #pragma unroll
            for (int o = 16; o; o >>= 1) {
                sm0 += __shfl_xor_sync(0xffffffffu, sm0, o);
                sm1 += __shfl_xor_sync(0xffffffffu, sm1, o);
            }
            float in0 = 1.0f / sm0, in1 = 1.0f / sm1;
            #pragma unroll
            for (int m = 0; m < 8; ++m) {
                int c = lane + (m << 5);
                float2 la0 = __half22float2(g_lamA2[gi0 * 256 + c]);
                float2 om0 = __half22float2(g_oml2[gi0 * 256 + c]);
                float2 la1 = __half22float2(g_lamA2[gi1 * 256 + c]);
                float2 om1 = __half22float2(g_oml2[gi1 * 256 + c]);
                tile[(i0 << 8) + c] = __floats2half2_rn(la0.x + om0.x * (a[m][0] * in0),
                                                        la0.y + om0.y * (a[m][1] * in0));
                tile[(i1 << 8) + c] = __floats2half2_rn(la1.x + om1.x * (a[m][2] * in1),
                                                        la1.y + om1.y * (a[m][3] * in1));
            }
        }
    }
    __syncthreads();
    CBAR();   // all cluster tiles hold M; peers' mbarrier inits visible

    // ---- phase 3: symmetrize + exp (DSMEM peer reads, reg-staged) ----
    {
        int i0 = (tid & 15) << 3;    // 8 rows
        int j0 = (tid >> 4) << 3;    // 8 cols (64 groups)
        uint4 pv[8];
        #pragma unroll
        for (int jj = 0; jj < 8; ++jj) {
            int j = j0 + jj;
            unsigned laddr = sbase + (unsigned)((((j & 127) << 9) + (rank << 7) + i0) << 1);
            unsigned raddr;
            asm volatile("mapa.shared::cluster.u32 %0, %1, %2;"
                         : "=r"(raddr) : "r"(laddr), "r"(j >> 7));
            asm volatile("ld.shared::cluster.v4.u32 {%0,%1,%2,%3}, [%4];"
                         : "=r"(pv[jj].x), "=r"(pv[jj].y), "=r"(pv[jj].z), "=r"(pv[jj].w)
                         : "r"(raddr));
        }
        CBAR();   // all reads done -> safe to overwrite
        #pragma unroll
        for (int ii = 0; ii < 8; ++ii) {
            int i = i0 + ii;
            __half2* rowp = &tile[(i << 8) + (j0 >> 1)];
            uint4 o0 = *(const uint4*)rowp;
            __half oh[8];
            *(uint4*)&oh[0] = o0;
            __half rh[8];
            #pragma unroll
            for (int jj = 0; jj < 8; ++jj) {
                float pe = __half2float(((const __half*)&pv[jj])[ii]);
                float ow = __half2float(oh[jj]);
                rh[jj] = __float2half_rn(__expf(0.5f * (ow + pe)));
            }
            *(uint4*)rowp = *(const uint4*)&rh[0];
        }
    }
    if (tid < 512) s_y[tid] = 1.0f;   // buffer 0 = ev_init
    __syncthreads();
    CBAR();   // all CTAs ready: tiles = E, s_y[0] = 1, mbar initialized everywhere

    // ---- phase 4: Sinkhorn, HSTEPS_ half-steps; mbarrier cluster sync ----
    int cur = 0;
    for (int hstep = 0; hstep < HSTEPS_; ++hstep) {
        const float* yb = &s_y[cur << 9];
        float4 ya0 = *(const float4*)&yb[lane * 8];
        float4 ya1 = *(const float4*)&yb[lane * 8 + 4];
        float4 yb0 = *(const float4*)&yb[256 + lane * 8];
        float4 yb1 = *(const float4*)&yb[256 + lane * 8 + 4];
        __half2 yh0 = __floats2half2_rn(ya0.x, ya0.y);
        __half2 yh1 = __floats2half2_rn(ya0.z, ya0.w);
        __half2 yh2 = __floats2half2_rn(ya1.x, ya1.y);
        __half2 yh3 = __floats2half2_rn(ya1.z, ya1.w);
        __half2 yh4 = __floats2half2_rn(yb0.x, yb0.y);
        __half2 yh5 = __floats2half2_rn(yb0.z, yb0.w);
        __half2 yh6 = __floats2half2_rn(yb1.x, yb1.y);
        __half2 yh7 = __floats2half2_rn(yb1.z, yb1.w);

        int nxt = cur ^ 1;
        #pragma unroll
        for (int rr = 0; rr < 4; ++rr) {
            int i = warp + rr * NW_;
            const uint4* rowq = (const uint4*)(tile + (i << 8));
            uint4 ea = rowq[lane];
            uint4 eb = rowq[lane + 32];
            __half2 a0 = __hmul2(*(const __half2*)&ea.x, yh0);
            a0 = __hfma2(*(const __half2*)&ea.y, yh1, a0);
            a0 = __hfma2(*(const __half2*)&ea.z, yh2, a0);
            a0 = __hfma2(*(const __half2*)&ea.w, yh3, a0);
            __half2 a1 = __hmul2(*(const __half2*)&eb.x, yh4);
            a1 = __hfma2(*(const __half2*)&eb.y, yh5, a1);
            a1 = __hfma2(*(const __half2*)&eb.z, yh6, a1);
            a1 = __hfma2(*(const __half2*)&eb.w, yh7, a1);
            float2 f0 = __half22float2(a0);
            float2 f1 = __half22float2(a1);
            float acc = f0.x + f0.y + f1.x + f1.y;
            #pragma unroll
            for (int o = 16; o; o >>= 1) acc += __shfl_xor_sync(0xffffffffu, acc, o);
            if (lane == 0) {
                float r = 1.0f / acc;
                if (!(hstep & 1)) s_ul[i] = r;
                unsigned laddr = sbase + (unsigned)(SM_Y + (((nxt << 9) + (rank << 7) + i) << 2));
                #pragma unroll
                for (int tr = 0; tr < 4; ++tr) {
                    unsigned raddr;
                    asm volatile("mapa.shared::cluster.u32 %0, %1, %2;"
                                 : "=r"(raddr) : "r"(laddr), "r"(tr));
                    asm volatile("st.shared::cluster.f32 [%0], %1;"
                                 :: "r"(raddr), "f"(r) : "memory");
                }
            }
        }
        // warp lane0: release-arrive on all 4 CTAs' mbarriers (orders prior remote stores)
        if (lane == 0) {
            #pragma unroll
            for (int tr = 0; tr < 4; ++tr) {
                asm volatile(
                    "{\n\t.reg .b32 ra;\n\t"
                    "mapa.shared::cluster.u32 ra, %0, %1;\n\t"
                    "mbarrier.arrive.release.cluster.shared::cluster.b64 _, [ra];\n\t}"
                    :: "r"(mbar), "r"(tr) : "memory");
            }
        }
        // all threads: acquire-wait on local mbarrier phase
        {
            unsigned parity = (unsigned)(hstep & 1);
            asm volatile(
                "{\n\t.reg .pred P;\n\t"
                "WLOOP_%=:\n\t"
                "mbarrier.try_wait.parity.acquire.cluster.shared::cta.b64 P, [%0], %1, 0x989680;\n\t"
                "@P bra.uni WDONE_%=;\n\t"
                "bra.uni WLOOP_%=;\n\t"
                "WDONE_%=:\n\t}"
                :: "r"(mbar), "r"(parity) : "memory");
        }
        cur ^= 1;
    }
    // s_y[cur] = final ev (512), s_ul = final eu (local 128)

    // ---- phase 5: Vs fp32 = V * ev ----
    {
        const __half2* V16 = g_v16 + hb * 8192;
        const float* evf = &s_y[cur << 9];
        for (int idx = tid; idx < 8192; idx += 1024) {
            int j = idx >> 4, c2 = idx & 15;
            float2 v = __half22float2(V16[idx]);
            float e = evf[j];
            Vs[(j << 5) + (c2 << 1)]     = v.x * e;
            Vs[(j << 5) + (c2 << 1) + 1] = v.y * e;
        }
    }
    __syncthreads();

    // ---- phase 6: out = eu * (E @ Vs), 4 rows per warp ----
    {
        float acc[4];
        #pragma unroll
        for (int r = 0; r < 4; ++r) acc[r] = 0.f;
        const __half2* trow = tile + ((warp << 2) << 8);
        #pragma unroll 2
        for (int c = 0; c < 256; ++c) {
            float vx = Vs[((c << 1) << 5) + lane];
            float vy = Vs[(((c << 1) + 1) << 5) + lane];
            #pragma unroll
            for (int r = 0; r < 4; ++r) {
                float2 p = __half22float2(trow[(r << 8) + c]);
                acc[r] += p.x * vx + p.y * vy;
            }
        }
        int h = hb >> 4, b = hb & 15;
        #pragma unroll
        for (int r = 0; r < 4; ++r) {
            int gi = (rank << 7) + (warp << 2) + r;
            out[(((size_t)(b * T_ + gi)) << 8) + (h << 5) + lane]
                = s_ul[(warp << 2) + r] * acc[r];
        }
    }
}

// ---------------- launch ----------------
extern "C" void kernel_launch(void* const* d_in, const int* in_sizes, int n_in,
                              void* d_out, int out_size) {
    const float* X  = (const float*)d_in[0];
    const float* te = (const float*)d_in[1];
    const float* Wq = (const float*)d_in[2];
    const float* Wk = (const float*)d_in[3];
    const float* Qb = (const float*)d_in[4];
    const float* Kb = (const float*)d_in[5];
    const float* WV = (const float*)d_in[6];
    const float* A  = (const float*)d_in[7];
    const float* L  = (const float*)d_in[8];
    float* out = (float*)d_out;

    cudaFuncSetAttribute(k57, cudaFuncAttributeMaxDynamicSharedMemorySize, SMEM57);

    k1_weights<<<T_, 256>>>(te, Wq, Wk);
    k2_tilde<<<dim3(64, 2, 8), 256>>>(Qb, Kb);
    k3_qkv<<<dim3(T_, 4), 256>>>(X, WV);
    k4_mix<<<T_, 256>>>(A, L);
    k57<<<HB_ * 4, 1024, SMEM57>>>(out);
}

// round 14
// speedup vs baseline: 1.0887x; 1.0887x over previous
#include <cuda_runtime.h>
#include <cuda_fp16.h>
#include <math.h>

#define B_ 16
#define T_ 512
#define D_ 256
#define H_ 8
#define E_ 32
#define BASIS_ 8
#define HB_ 128          // H_*B_
#define HE_ 256          // H_*E_

// ---------------- scratch (static device globals; no allocation) ----------------
__device__ float   g_qw[T_*BASIS_];
__device__ float   g_kw[T_*BASIS_];
__device__ __half2 g_Qt16[T_*D_*HE_/2];    // 67MB
__device__ __half2 g_Kt16[T_*D_*HE_/2];    // 67MB
__device__ float   g_q[HB_*T_*E_];         // [h][b][t][e] fp32
__device__ float   g_k[HB_*T_*E_];
__device__ __half2 g_v16[HB_*T_*E_/2];     // [h][b][t][e] fp16
__device__ __half2 g_lamA2[T_*256];
__device__ __half2 g_oml2[T_*256];

// ---------------- K1: per-token basis mixing weights ----------------
__global__ void k1_weights(const float* __restrict__ te,
                           const float* __restrict__ Wq,
                           const float* __restrict__ Wk) {
    int t = blockIdx.x;
    int warp = threadIdx.x >> 5, lane = threadIdx.x & 31;
    const float* tr = te + t * D_;
    const float* wq = Wq + (t * BASIS_ + warp) * D_;
    const float* wk = Wk + (t * BASIS_ + warp) * D_;
    float aq = 0.f, ak = 0.f;
    #pragma unroll
    for (int m = 0; m < D_ / 32; ++m) {
        int d = lane + 32 * m;
        float x = tr[d];
        aq += x * wq[d];
        ak += x * wk[d];
    }
    #pragma unroll
    for (int o = 16; o; o >>= 1) {
        aq += __shfl_xor_sync(0xffffffffu, aq, o);
        ak += __shfl_xor_sync(0xffffffffu, ak, o);
    }
    if (lane == 0) {
        g_qw[t * BASIS_ + warp] = aq;
        g_kw[t * BASIS_ + warp] = ak;
    }
}

// ---------------- K2: Q_tilde / K_tilde build (fp16 out), t-chunked ----------------
__global__ __launch_bounds__(256) void k2_tilde(const float* __restrict__ Qb,
                                                const float* __restrict__ Kb) {
    __shared__ float sW[64 * BASIS_];
    int qk = blockIdx.y;
    int t0 = blockIdx.z << 6;
    const float* W = (qk ? g_kw : g_qw) + t0 * BASIS_;
    const float* Bs = qk ? Kb : Qb;
    uint2* Out = qk ? (uint2*)g_Kt16 : (uint2*)g_Qt16;
    for (int idx = threadIdx.x; idx < 64 * BASIS_; idx += 256) sW[idx] = W[idx];
    __syncthreads();

    int f4 = blockIdx.x * 256 + threadIdx.x;
    float4 b4[BASIS_];
    #pragma unroll
    for (int k = 0; k < BASIS_; ++k) b4[k] = ((const float4*)Bs)[k * 16384 + f4];

    for (int tt = 0; tt < 64; ++tt) {
        float4 a = make_float4(0.f, 0.f, 0.f, 0.f);
        #pragma unroll
        for (int k = 0; k < BASIS_; ++k) {
            float w = sW[tt * BASIS_ + k];
            a.x += w * b4[k].x; a.y += w * b4[k].y;
            a.z += w * b4[k].z; a.w += w * b4[k].w;
        }
        __half2 h0 = __floats2half2_rn(a.x, a.y);
        __half2 h1 = __floats2half2_rn(a.z, a.w);
        uint2 u;
        u.x = *(const unsigned int*)&h0;
        u.y = *(const unsigned int*)&h1;
        Out[(t0 + tt) * 16384 + f4] = u;
    }
}

// ---------------- K3: q/k/v projections ----------------
__global__ __launch_bounds__(256) void k3_qkv(const float* __restrict__ X,
                                              const float* __restrict__ WV) {
    __shared__ float xsT[D_][16];
    int t = blockIdx.x, m = blockIdx.y;

    for (int idx = threadIdx.x; idx < B_ * D_; idx += 256) {
        int b = idx >> 8, d = idx & 255;
        xsT[d][b] = X[((size_t)b * T_ + t) * D_ + d];
    }
    __syncthreads();

    int tc = threadIdx.x & 31;
    int tb = threadIdx.x >> 5;

    if (m < 2) {
        float acc[2][8];
        #pragma unroll
        for (int i = 0; i < 2; ++i)
            #pragma unroll
            for (int j = 0; j < 8; ++j) acc[i][j] = 0.f;
        const uint4* W = (const uint4*)((m == 0 ? g_Qt16 : g_Kt16) + (size_t)t * 32768);
        #pragma unroll 8
        for (int d = 0; d < D_; ++d) {
            float2 xv = *(const float2*)&xsT[d][tb << 1];
            uint4 wr = W[(d << 5) + tc];
            float2 w0 = __half22float2(*(const __half2*)&wr.x);
            float2 w1 = __half22float2(*(const __half2*)&wr.y);
            float2 w2 = __half22float2(*(const __half2*)&wr.z);
            float2 w3 = __half22float2(*(const __half2*)&wr.w);
            acc[0][0] += xv.x * w0.x; acc[0][1] += xv.x * w0.y;
            acc[0][2] += xv.x * w1.x; acc[0][3] += xv.x * w1.y;
            acc[0][4] += xv.x * w2.x; acc[0][5] += xv.x * w2.y;
            acc[0][6] += xv.x * w3.x; acc[0][7] += xv.x * w3.y;
            acc[1][0] += xv.y * w0.x; acc[1][1] += xv.y * w0.y;
            acc[1][2] += xv.y * w1.x; acc[1][3] += xv.y * w1.y;
            acc[1][4] += xv.y * w2.x; acc[1][5] += xv.y * w2.y;
            acc[1][6] += xv.y * w3.x; acc[1][7] += xv.y * w3.y;
        }
        float* Out = (m == 0) ? g_q : g_k;
        int e0 = tc << 3;
        int h = e0 >> 5, eo = e0 & 31;
        #pragma unroll
        for (int i = 0; i < 2; ++i) {
            int b = (tb << 1) + i;
            size_t base = (((size_t)(h * B_ + b) * T_ + t) << 5) + eo;
            *(float4*)&Out[base]     = make_float4(acc[i][0], acc[i][1], acc[i][2], acc[i][3]);
            *(float4*)&Out[base + 4] = make_float4(acc[i][4], acc[i][5], acc[i][6], acc[i][7]);
        }
    } else {
        float acc[2][4];
        #pragma unroll
        for (int i = 0; i < 2; ++i)
            #pragma unroll
            for (int j = 0; j < 4; ++j) acc[i][j] = 0.f;
        int e0 = ((m - 2) << 7) + (tc << 2);
        const float* W = WV + (size_t)t * 65536;
        #pragma unroll 8
        for (int d = 0; d < D_; ++d) {
            float2 xv = *(const float2*)&xsT[d][tb << 1];
            float4 wv = *(const float4*)&W[(d << 8) + e0];
            acc[0][0] += xv.x * wv.x; acc[0][1] += xv.x * wv.y;
            acc[0][2] += xv.x * wv.z; acc[0][3] += xv.x * wv.w;
            acc[1][0] += xv.y * wv.x; acc[1][1] += xv.y * wv.y;
            acc[1][2] += xv.y * wv.z; acc[1][3] += xv.y * wv.w;
        }
        int h = e0 >> 5, eo = e0 & 31;
        #pragma unroll
        for (int i = 0; i < 2; ++i) {
            int b = (tb << 1) + i;
            __half2 h0 = __floats2half2_rn(acc[i][0], acc[i][1]);
            __half2 h1 = __floats2half2_rn(acc[i][2], acc[i][3]);
            uint2 u;
            u.x = *(const unsigned int*)&h0;
            u.y = *(const unsigned int*)&h1;
            *(uint2*)&g_v16[(((size_t)(h * B_ + b) * T_ + t) << 4) + (eo >> 1)] = u;
        }
    }
}

// ---------------- K4: mixing coefficients (half2 out) ----------------
__global__ void k4_mix(const float* __restrict__ A, const float* __restrict__ L) {
    int t = blockIdx.x, c = threadIdx.x;
    int j0 = c << 1, j1 = j0 + 1;
    float a0 = 0.5f * (A[t * T_ + j0] + A[j0 * T_ + t]);
    float a1 = 0.5f * (A[t * T_ + j1] + A[j1 * T_ + t]);
    float lam0 = 1.0f / (1.0f + __expf(-L[t * T_ + j0]));
    float lam1 = 1.0f / (1.0f + __expf(-L[t * T_ + j1]));
    g_lamA2[t * 256 + c] = __floats2half2_rn(lam0 * a0, lam1 * a1);
    g_oml2[t * 256 + c]  = __floats2half2_rn(1.0f - lam0, 1.0f - lam1);
}

// ---------------- K57: fused scores+softmax+mix+symexp+Sinkhorn+PV ----------------
#define SM_UNION 131072
#define SM_Y     196864
#define SM_UL    200960
#define SMEM57   201472
#define NW_      32       // warps per CTA
#define HSTEPS_  20       // 10 Sinkhorn iterations (converged ~5e-6 << fp16 noise; R12-validated)

#define CBAR() do { \
    asm volatile("barrier.cluster.arrive.aligned;" ::: "memory"); \
    asm volatile("barrier.cluster.wait.aligned;"  ::: "memory"); } while (0)

__global__ __launch_bounds__(1024) __cluster_dims__(4, 1, 1)
void k57(float* __restrict__ out) {
    extern __shared__ char sm[];
    __half2* tile = (__half2*)sm;                 // [128][256] half2 = M/E rows fp16
    float2*  kT2  = (float2*)(sm + SM_UNION);     // [32][257] float2 (phase 1-2)
    float*   Vs   = (float*)(sm + SM_UNION);      // [512][32] f32 (loaded pre-phase-4)
    float*   s_y  = (float*)(sm + SM_Y);          // [2][512]
    float*   s_ul = (float*)(sm + SM_UL);         // [128]

    int tid = threadIdx.x;
    int hb = blockIdx.x >> 2;
    int rank = blockIdx.x & 3;
    int warp = tid >> 5, lane = tid & 31;

    unsigned sbase;
    asm("{ .reg .u64 t; cvta.to.shared.u64 t, %1; cvt.u32.u64 %0, t; }"
        : "=r"(sbase) : "l"(sm));

    // ---- phase 1: K transpose into kT2 ----
    const float* K = g_k + hb * (T_ * E_);
    for (int idx = tid; idx < T_ * E_; idx += 1024) {
        int t = idx >> 5, e = idx & 31;
        ((float*)&kT2[e * 257 + (t >> 1)])[t & 1] = K[idx];
    }
    __syncthreads();

    // ---- phase 2: scores + softmax + mix -> tile (fp16 M, local rows) ----
    {
        const float* Q = g_q + hb * (T_ * E_);
        const float SC = 0.17677669529663687f;
        for (int p = warp; p < 64; p += NW_) {
            int i0 = p << 1, i1 = i0 + 1;
            int gi0 = (rank << 7) + i0, gi1 = gi0 + 1;
            float q0 = Q[(gi0 << 5) + lane];
            float q1 = Q[(gi1 << 5) + lane];
            float a[8][4];
            #pragma unroll
            for (int m = 0; m < 8; ++m) { a[m][0] = a[m][1] = a[m][2] = a[m][3] = 0.f; }
            #pragma unroll
            for (int d = 0; d < 32; ++d) {
                float qd0 = __shfl_sync(0xffffffffu, q0, d);
                float qd1 = __shfl_sync(0xffffffffu, q1, d);
                const float2* row = &kT2[d * 257];
                #pragma unroll
                for (int m = 0; m < 8; ++m) {
                    float2 kv = row[lane + (m << 5)];
                    a[m][0] += qd0 * kv.x; a[m][1] += qd0 * kv.y;
                    a[m][2] += qd1 * kv.x; a[m][3] += qd1 * kv.y;
                }
            }
            float mx0 = -1e30f, mx1 = -1e30f;
            #pragma unroll
            for (int m = 0; m < 8; ++m) {
                a[m][0] *= SC; a[m][1] *= SC; a[m][2] *= SC; a[m][3] *= SC;
                mx0 = fmaxf(mx0, fmaxf(a[m][0], a[m][1]));
                mx1 = fmaxf(mx1, fmaxf(a[m][2], a[m][3]));
            }
            #pragma unroll
            for (int o = 16; o; o >>= 1) {
                mx0 = fmaxf(mx0, __shfl_xor_sync(0xffffffffu, mx0, o));
                mx1 = fmaxf(mx1, __shfl_xor_sync(0xffffffffu, mx1, o));
            }
            float sm0 = 0.f, sm1 = 0.f;
            #pragma unroll
            for (int m = 0; m < 8; ++m) {
                a[m][0] = __expf(a[m][0] - mx0); a[m][1] = __expf(a[m][1] - mx0);
                a[m][2] = __expf(a[m][2] - mx1); a[m][3] = __expf(a[m][3] - mx1);
                sm0 += a[m][0] + a[m][1];
                sm1 += a[m][2] + a[m][3];
            }
            #pragma unroll
            for (int o = 16; o; o >>= 1) {
                sm0 += __shfl_xor_sync(0xffffffffu, sm0, o);
                sm1 += __shfl_xor_sync(0xffffffffu, sm1, o);
            }
            float in0 = 1.0f / sm0, in1 = 1.0f / sm1;
            #pragma unroll
            for (int m = 0; m < 8; ++m) {
                int c = lane + (m << 5);
                float2 la0 = __half22float2(g_lamA2[gi0 * 256 + c]);
                float2 om0 = __half22float2(g_oml2[gi0 * 256 + c]);
                float2 la1 = __half22float2(g_lamA2[gi1 * 256 + c]);
                float2 om1 = __half22float2(g_oml2[gi1 * 256 + c]);
                tile[(i0 << 8) + c] = __floats2half2_rn(la0.x + om0.x * (a[m][0] * in0),
                                                        la0.y + om0.y * (a[m][1] * in0));
                tile[(i1 << 8) + c] = __floats2half2_rn(la1.x + om1.x * (a[m][2] * in1),
                                                        la1.y + om1.y * (a[m][3] * in1));
            }
        }
    }
    __syncthreads();
    CBAR();   // all cluster tiles hold M

    // ---- phase 3: symmetrize + exp (DSMEM peer reads, reg-staged) ----
    {
        int i0 = (tid & 15) << 3;    // 8 rows
        int j0 = (tid >> 4) << 3;    // 8 cols (64 groups)
        uint4 pv[8];
        #pragma unroll
        for (int jj = 0; jj < 8; ++jj) {
            int j = j0 + jj;
            unsigned laddr = sbase + (unsigned)((((j & 127) << 9) + (rank << 7) + i0) << 1);
            unsigned raddr;
            asm volatile("mapa.shared::cluster.u32 %0, %1, %2;"
                         : "=r"(raddr) : "r"(laddr), "r"(j >> 7));
            asm volatile("ld.shared::cluster.v4.u32 {%0,%1,%2,%3}, [%4];"
                         : "=r"(pv[jj].x), "=r"(pv[jj].y), "=r"(pv[jj].z), "=r"(pv[jj].w)
                         : "r"(raddr));
        }
        CBAR();   // all reads done -> safe to overwrite
        #pragma unroll
        for (int ii = 0; ii < 8; ++ii) {
            int i = i0 + ii;
            __half2* rowp = &tile[(i << 8) + (j0 >> 1)];
            uint4 o0 = *(const uint4*)rowp;
            __half oh[8];
            *(uint4*)&oh[0] = o0;
            __half rh[8];
            #pragma unroll
            for (int jj = 0; jj < 8; ++jj) {
                float pe = __half2float(((const __half*)&pv[jj])[ii]);
                float ow = __half2float(oh[jj]);
                rh[jj] = __float2half_rn(__expf(0.5f * (ow + pe)));
            }
            *(uint4*)rowp = *(const uint4*)&rh[0];
        }
    }
    if (tid < 512) s_y[tid] = 1.0f;   // buffer 0 = ev_init

    // ---- hoisted V load: raw V fp32 into Vs (region dead after phase 2) ----
    {
        const __half2* V16 = g_v16 + hb * 8192;
        for (int idx = tid; idx < 8192; idx += 1024) {
            int j = idx >> 4, c2 = idx & 15;
            float2 v = __half22float2(V16[idx]);
            Vs[(j << 5) + (c2 << 1)]     = v.x;
            Vs[(j << 5) + (c2 << 1) + 1] = v.y;
        }
    }
    __syncthreads();

    // ---- phase 4: Sinkhorn, HSTEPS_ half-steps (uint4 + HFMA2 chunks) ----
    int cur = 0;
    for (int hstep = 0; hstep < HSTEPS_; ++hstep) {
        const float* yb = &s_y[cur << 9];
        float4 ya0 = *(const float4*)&yb[lane * 8];
        float4 ya1 = *(const float4*)&yb[lane * 8 + 4];
        float4 yb0 = *(const float4*)&yb[256 + lane * 8];
        float4 yb1 = *(const float4*)&yb[256 + lane * 8 + 4];
        __half2 yh0 = __floats2half2_rn(ya0.x, ya0.y);
        __half2 yh1 = __floats2half2_rn(ya0.z, ya0.w);
        __half2 yh2 = __floats2half2_rn(ya1.x, ya1.y);
        __half2 yh3 = __floats2half2_rn(ya1.z, ya1.w);
        __half2 yh4 = __floats2half2_rn(yb0.x, yb0.y);
        __half2 yh5 = __floats2half2_rn(yb0.z, yb0.w);
        __half2 yh6 = __floats2half2_rn(yb1.x, yb1.y);
        __half2 yh7 = __floats2half2_rn(yb1.z, yb1.w);

        int nxt = cur ^ 1;
        #pragma unroll
        for (int rr = 0; rr < 4; ++rr) {
            int i = warp + rr * NW_;
            const uint4* rowq = (const uint4*)(tile + (i << 8));
            uint4 ea = rowq[lane];
            uint4 eb = rowq[lane + 32];
            __half2 a0 = __hmul2(*(const __half2*)&ea.x, yh0);
            a0 = __hfma2(*(const __half2*)&ea.y, yh1, a0);
            a0 = __hfma2(*(const __half2*)&ea.z, yh2, a0);
            a0 = __hfma2(*(const __half2*)&ea.w, yh3, a0);
            __half2 a1 = __hmul2(*(const __half2*)&eb.x, yh4);
            a1 = __hfma2(*(const __half2*)&eb.y, yh5, a1);
            a1 = __hfma2(*(const __half2*)&eb.z, yh6, a1);
            a1 = __hfma2(*(const __half2*)&eb.w, yh7, a1);
            float2 f0 = __half22float2(a0);
            float2 f1 = __half22float2(a1);
            float acc = f0.x + f0.y + f1.x + f1.y;
            #pragma unroll
            for (int o = 16; o; o >>= 1) acc += __shfl_xor_sync(0xffffffffu, acc, o);
            if (lane == 0) {
                float r = 1.0f / acc;
                if (!(hstep & 1)) s_ul[i] = r;
                unsigned laddr = sbase + (unsigned)(SM_Y + (((nxt << 9) + (rank << 7) + i) << 2));
                #pragma unroll
                for (int tr = 0; tr < 4; ++tr) {
                    unsigned raddr;
                    asm volatile("mapa.shared::cluster.u32 %0, %1, %2;"
                                 : "=r"(raddr) : "r"(laddr), "r"(tr));
                    asm volatile("st.shared::cluster.f32 [%0], %1;"
                                 :: "r"(raddr), "f"(r) : "memory");
                }
            }
        }
        CBAR();
        cur ^= 1;
    }
    // s_y[cur] = final ev (512), s_ul = final eu (local 128)

    // ---- phase 5: scale Vs in place by ev ----
    {
        const float* evf = &s_y[cur << 9];
        for (int idx = tid; idx < 8192; idx += 1024) {
            int j = idx >> 4, c2 = idx & 15;
            float e = evf[j];
            Vs[(j << 5) + (c2 << 1)]     *= e;
            Vs[(j << 5) + (c2 << 1) + 1] *= e;
        }
    }
    __syncthreads();

    // ---- phase 6: out = eu * (E @ Vs), 4 rows per warp ----
    {
        float acc[4];
        #pragma unroll
        for (int r = 0; r < 4; ++r) acc[r] = 0.f;
        const __half2* trow = tile + ((warp << 2) << 8);
        #pragma unroll 2
        for (int c = 0; c < 256; ++c) {
            float vx = Vs[((c << 1) << 5) + lane];
            float vy = Vs[(((c << 1) + 1) << 5) + lane];
            #pragma unroll
            for (int r = 0; r < 4; ++r) {
                float2 p = __half22float2(trow[(r << 8) + c]);
                acc[r] += p.x * vx + p.y * vy;
            }
        }
        int h = hb >> 4, b = hb & 15;
        #pragma unroll
        for (int r = 0; r < 4; ++r) {
            int gi = (rank << 7) + (warp << 2) + r;
            out[(((size_t)(b * T_ + gi)) << 8) + (h << 5) + lane]
                = s_ul[(warp << 2) + r] * acc[r];
        }
    }
}

// ---------------- launch ----------------
extern "C" void kernel_launch(void* const* d_in, const int* in_sizes, int n_in,
                              void* d_out, int out_size) {
    const float* X  = (const float*)d_in[0];
    const float* te = (const float*)d_in[1];
    const float* Wq = (const float*)d_in[2];
    const float* Wk = (const float*)d_in[3];
    const float* Qb = (const float*)d_in[4];
    const float* Kb = (const float*)d_in[5];
    const float* WV = (const float*)d_in[6];
    const float* A  = (const float*)d_in[7];
    const float* L  = (const float*)d_in[8];
    float* out = (float*)d_out;

    cudaFuncSetAttribute(k57, cudaFuncAttributeMaxDynamicSharedMemorySize, SMEM57);

    k1_weights<<<T_, 256>>>(te, Wq, Wk);
    k2_tilde<<<dim3(64, 2, 8), 256>>>(Qb, Kb);
    k3_qkv<<<dim3(T_, 4), 256>>>(X, WV);
    k4_mix<<<T_, 256>>>(A, L);
    k57<<<HB_ * 4, 1024, SMEM57>>>(out);
}

// round 15
// speedup vs baseline: 1.0936x; 1.0045x over previous
#include <cuda_runtime.h>
#include <cuda_fp16.h>
#include <math.h>

#define B_ 16
#define T_ 512
#define D_ 256
#define H_ 8
#define E_ 32
#define BASIS_ 8
#define HB_ 128          // H_*B_
#define HE_ 256          // H_*E_

// ---------------- scratch (static device globals; no allocation) ----------------
__device__ float   g_qw[T_*BASIS_];
__device__ float   g_kw[T_*BASIS_];
__device__ __half2 g_Qt16[T_*D_*HE_/2];    // 67MB
__device__ __half2 g_Kt16[T_*D_*HE_/2];    // 67MB
__device__ float   g_q[HB_*T_*E_];         // [h][b][t][e] fp32
__device__ float   g_k[HB_*T_*E_];
__device__ __half2 g_v16[HB_*T_*E_/2];     // [h][b][t][e] fp16
__device__ __half2 g_lamA2[T_*256];
__device__ __half2 g_oml2[T_*256];

// ---------------- K1: per-token basis mixing weights ----------------
__global__ void k1_weights(const float* __restrict__ te,
                           const float* __restrict__ Wq,
                           const float* __restrict__ Wk) {
    int t = blockIdx.x;
    int warp = threadIdx.x >> 5, lane = threadIdx.x & 31;
    const float* tr = te + t * D_;
    const float* wq = Wq + (t * BASIS_ + warp) * D_;
    const float* wk = Wk + (t * BASIS_ + warp) * D_;
    float aq = 0.f, ak = 0.f;
    #pragma unroll
    for (int m = 0; m < D_ / 32; ++m) {
        int d = lane + 32 * m;
        float x = tr[d];
        aq += x * wq[d];
        ak += x * wk[d];
    }
    #pragma unroll
    for (int o = 16; o; o >>= 1) {
        aq += __shfl_xor_sync(0xffffffffu, aq, o);
        ak += __shfl_xor_sync(0xffffffffu, ak, o);
    }
    if (lane == 0) {
        g_qw[t * BASIS_ + warp] = aq;
        g_kw[t * BASIS_ + warp] = ak;
    }
}

// ---------------- KA: merged k2_tilde + V projection + k4_mix (independent work) ----
// bid < 1024       : k2_tilde block  (f4blk = bid&63, qk = (bid>>6)&1, t0blk = bid>>7)
// 1024 <= bid <2048: V projection    (t = (bid-1024)>>1, half = (bid-1024)&1)
// bid >= 2048      : k4_mix          (t = bid-2048)
__global__ __launch_bounds__(256) void kA(const float* __restrict__ Qb,
                                          const float* __restrict__ Kb,
                                          const float* __restrict__ X,
                                          const float* __restrict__ WV,
                                          const float* __restrict__ A,
                                          const float* __restrict__ L) {
    __shared__ float smem[4096];   // k2: sW[512]; V: xsT[256][16]
    int bid = blockIdx.x;
    int tid = threadIdx.x;

    if (bid < 1024) {
        // ---- k2_tilde ----
        float* sW = smem;
        int f4blk = bid & 63, qk = (bid >> 6) & 1, t0 = (bid >> 7) << 6;
        const float* W = (qk ? g_kw : g_qw) + t0 * BASIS_;
        const float* Bs = qk ? Kb : Qb;
        uint2* Out = qk ? (uint2*)g_Kt16 : (uint2*)g_Qt16;
        for (int idx = tid; idx < 64 * BASIS_; idx += 256) sW[idx] = W[idx];
        __syncthreads();

        int f4 = f4blk * 256 + tid;
        float4 b4[BASIS_];
        #pragma unroll
        for (int k = 0; k < BASIS_; ++k) b4[k] = ((const float4*)Bs)[k * 16384 + f4];

        for (int tt = 0; tt < 64; ++tt) {
            float4 a = make_float4(0.f, 0.f, 0.f, 0.f);
            #pragma unroll
            for (int k = 0; k < BASIS_; ++k) {
                float w = sW[tt * BASIS_ + k];
                a.x += w * b4[k].x; a.y += w * b4[k].y;
                a.z += w * b4[k].z; a.w += w * b4[k].w;
            }
            __half2 h0 = __floats2half2_rn(a.x, a.y);
            __half2 h1 = __floats2half2_rn(a.z, a.w);
            uint2 u;
            u.x = *(const unsigned int*)&h0;
            u.y = *(const unsigned int*)&h1;
            Out[(t0 + tt) * 16384 + f4] = u;
        }
    } else if (bid < 2048) {
        // ---- V projection (fp32 W -> fp16 out), column half per block ----
        float* xsT = smem;   // [256][16]
        int t = (bid - 1024) >> 1, half = (bid - 1024) & 1;
        for (int idx = tid; idx < B_ * D_; idx += 256) {
            int b = idx >> 8, d = idx & 255;
            xsT[d * 16 + b] = X[((size_t)b * T_ + t) * D_ + d];
        }
        __syncthreads();

        int tc = tid & 31;
        int tb = tid >> 5;
        float acc[2][4];
        #pragma unroll
        for (int i = 0; i < 2; ++i)
            #pragma unroll
            for (int j = 0; j < 4; ++j) acc[i][j] = 0.f;
        int e0 = (half << 7) + (tc << 2);
        const float* W = WV + (size_t)t * 65536;
        #pragma unroll 8
        for (int d = 0; d < D_; ++d) {
            float2 xv = *(const float2*)&xsT[d * 16 + (tb << 1)];
            float4 wv = *(const float4*)&W[(d << 8) + e0];
            acc[0][0] += xv.x * wv.x; acc[0][1] += xv.x * wv.y;
            acc[0][2] += xv.x * wv.z; acc[0][3] += xv.x * wv.w;
            acc[1][0] += xv.y * wv.x; acc[1][1] += xv.y * wv.y;
            acc[1][2] += xv.y * wv.z; acc[1][3] += xv.y * wv.w;
        }
        int h = e0 >> 5, eo = e0 & 31;
        #pragma unroll
        for (int i = 0; i < 2; ++i) {
            int b = (tb << 1) + i;
            __half2 h0 = __floats2half2_rn(acc[i][0], acc[i][1]);
            __half2 h1 = __floats2half2_rn(acc[i][2], acc[i][3]);
            uint2 u;
            u.x = *(const unsigned int*)&h0;
            u.y = *(const unsigned int*)&h1;
            *(uint2*)&g_v16[(((size_t)(h * B_ + b) * T_ + t) << 4) + (eo >> 1)] = u;
        }
    } else {
        // ---- k4_mix ----
        int t = bid - 2048, c = tid;
        int j0 = c << 1, j1 = j0 + 1;
        float a0 = 0.5f * (A[t * T_ + j0] + A[j0 * T_ + t]);
        float a1 = 0.5f * (A[t * T_ + j1] + A[j1 * T_ + t]);
        float lam0 = 1.0f / (1.0f + __expf(-L[t * T_ + j0]));
        float lam1 = 1.0f / (1.0f + __expf(-L[t * T_ + j1]));
        g_lamA2[t * 256 + c] = __floats2half2_rn(lam0 * a0, lam1 * a1);
        g_oml2[t * 256 + c]  = __floats2half2_rn(1.0f - lam0, 1.0f - lam1);
    }
}

// ---------------- K3: q/k projections (fp16 W) ----------------
__global__ __launch_bounds__(256) void k3_qk(const float* __restrict__ X) {
    __shared__ float xsT[D_][16];
    int t = blockIdx.x, m = blockIdx.y;

    for (int idx = threadIdx.x; idx < B_ * D_; idx += 256) {
        int b = idx >> 8, d = idx & 255;
        xsT[d][b] = X[((size_t)b * T_ + t) * D_ + d];
    }
    __syncthreads();

    int tc = threadIdx.x & 31;
    int tb = threadIdx.x >> 5;

    float acc[2][8];
    #pragma unroll
    for (int i = 0; i < 2; ++i)
        #pragma unroll
        for (int j = 0; j < 8; ++j) acc[i][j] = 0.f;
    const uint4* W = (const uint4*)((m == 0 ? g_Qt16 : g_Kt16) + (size_t)t * 32768);
    #pragma unroll 8
    for (int d = 0; d < D_; ++d) {
        float2 xv = *(const float2*)&xsT[d][tb << 1];
        uint4 wr = W[(d << 5) + tc];
        float2 w0 = __half22float2(*(const __half2*)&wr.x);
        float2 w1 = __half22float2(*(const __half2*)&wr.y);
        float2 w2 = __half22float2(*(const __half2*)&wr.z);
        float2 w3 = __half22float2(*(const __half2*)&wr.w);
        acc[0][0] += xv.x * w0.x; acc[0][1] += xv.x * w0.y;
        acc[0][2] += xv.x * w1.x; acc[0][3] += xv.x * w1.y;
        acc[0][4] += xv.x * w2.x; acc[0][5] += xv.x * w2.y;
        acc[0][6] += xv.x * w3.x; acc[0][7] += xv.x * w3.y;
        acc[1][0] += xv.y * w0.x; acc[1][1] += xv.y * w0.y;
        acc[1][2] += xv.y * w1.x; acc[1][3] += xv.y * w1.y;
        acc[1][4] += xv.y * w2.x; acc[1][5] += xv.y * w2.y;
        acc[1][6] += xv.y * w3.x; acc[1][7] += xv.y * w3.y;
    }
    float* Out = (m == 0) ? g_q : g_k;
    int e0 = tc << 3;
    int h = e0 >> 5, eo = e0 & 31;
    #pragma unroll
    for (int i = 0; i < 2; ++i) {
        int b = (tb << 1) + i;
        size_t base = (((size_t)(h * B_ + b) * T_ + t) << 5) + eo;
        *(float4*)&Out[base]     = make_float4(acc[i][0], acc[i][1], acc[i][2], acc[i][3]);
        *(float4*)&Out[base + 4] = make_float4(acc[i][4], acc[i][5], acc[i][6], acc[i][7]);
    }
}

// ---------------- K57: fused scores+softmax+mix+symexp+Sinkhorn+PV ----------------
#define SM_UNION 131072
#define SM_Y     196864
#define SM_UL    200960
#define SMEM57   201472
#define NW_      32       // warps per CTA
#define HSTEPS_  16       // 8 Sinkhorn iterations (residual <=1.4e-5 << fp16 noise)

#define CBAR() do { \
    asm volatile("barrier.cluster.arrive.aligned;" ::: "memory"); \
    asm volatile("barrier.cluster.wait.aligned;"  ::: "memory"); } while (0)

__global__ __launch_bounds__(1024) __cluster_dims__(4, 1, 1)
void k57(float* __restrict__ out) {
    extern __shared__ char sm[];
    __half2* tile = (__half2*)sm;                 // [128][256] half2 = M/E rows fp16
    float2*  kT2  = (float2*)(sm + SM_UNION);     // [32][257] float2 (phase 1-2)
    float2*  Vs2  = (float2*)(sm + SM_UNION);     // [256][32] float2: (V[2c][e], V[2c+1][e])
    float*   s_y  = (float*)(sm + SM_Y);          // [2][512]
    float*   s_ul = (float*)(sm + SM_UL);         // [128]

    int tid = threadIdx.x;
    int hb = blockIdx.x >> 2;
    int rank = blockIdx.x & 3;
    int warp = tid >> 5, lane = tid & 31;

    unsigned sbase;
    asm("{ .reg .u64 t; cvta.to.shared.u64 t, %1; cvt.u32.u64 %0, t; }"
        : "=r"(sbase) : "l"(sm));

    // ---- phase 1: K transpose into kT2 ----
    const float* K = g_k + hb * (T_ * E_);
    for (int idx = tid; idx < T_ * E_; idx += 1024) {
        int t = idx >> 5, e = idx & 31;
        ((float*)&kT2[e * 257 + (t >> 1)])[t & 1] = K[idx];
    }
    __syncthreads();

    // ---- phase 2: scores + softmax + mix -> tile (fp16 M, local rows) ----
    {
        const float* Q = g_q + hb * (T_ * E_);
        const float SC = 0.17677669529663687f;
        for (int p = warp; p < 64; p += NW_) {
            int i0 = p << 1, i1 = i0 + 1;
            int gi0 = (rank << 7) + i0, gi1 = gi0 + 1;
            float q0 = Q[(gi0 << 5) + lane];
            float q1 = Q[(gi1 << 5) + lane];
            float a[8][4];
            #pragma unroll
            for (int m = 0; m < 8; ++m) { a[m][0] = a[m][1] = a[m][2] = a[m][3] = 0.f; }
            #pragma unroll
            for (int d = 0; d < 32; ++d) {
                float qd0 = __shfl_sync(0xffffffffu, q0, d);
                float qd1 = __shfl_sync(0xffffffffu, q1, d);
                const float2* row = &kT2[d * 257];
                #pragma unroll
                for (int m = 0; m < 8; ++m) {
                    float2 kv = row[lane + (m << 5)];
                    a[m][0] += qd0 * kv.x; a[m][1] += qd0 * kv.y;
                    a[m][2] += qd1 * kv.x; a[m][3] += qd1 * kv.y;
                }
            }
            float mx0 = -1e30f, mx1 = -1e30f;
            #pragma unroll
            for (int m = 0; m < 8; ++m) {
                a[m][0] *= SC; a[m][1] *= SC; a[m][2] *= SC; a[m][3] *= SC;
                mx0 = fmaxf(mx0, fmaxf(a[m][0], a[m][1]));
                mx1 = fmaxf(mx1, fmaxf(a[m][2], a[m][3]));
            }
            #pragma unroll
            for (int o = 16; o; o >>= 1) {
                mx0 = fmaxf(mx0, __shfl_xor_sync(0xffffffffu, mx0, o));
                mx1 = fmaxf(mx1, __shfl_xor_sync(0xffffffffu, mx1, o));
            }
            float sm0 = 0.f, sm1 = 0.f;
            #pragma unroll
            for (int m = 0; m < 8; ++m) {
                a[m][0] = __expf(a[m][0] - mx0); a[m][1] = __expf(a[m][1] - mx0);
                a[m][2] = __expf(a[m][2] - mx1); a[m][3] = __expf(a[m][3] - mx1);
                sm0 += a[m][0] + a[m][1];
                sm1 += a[m][2] + a[m][3];
            }
            #pragma unroll
            for (int o = 16; o; o >>= 1) {
                sm0 += __shfl_xor_sync(0xffffffffu, sm0, o);
                sm1 += __shfl_xor_sync(0xffffffffu, sm1, o);
            }
            float in0 = 1.0f / sm0, in1 = 1.0f / sm1;
            #pragma unroll
            for (int m = 0; m < 8; ++m) {
                int c = lane + (m << 5);
                float2 la0 = __half22float2(g_lamA2[gi0 * 256 + c]);
                float2 om0 = __half22float2(g_oml2[gi0 * 256 + c]);
                float2 la1 = __half22float2(g_lamA2[gi1 * 256 + c]);
                float2 om1 = __half22float2(g_oml2[gi1 * 256 + c]);
                tile[(i0 << 8) + c] = __floats2half2_rn(la0.x + om0.x * (a[m][0] * in0),
                                                        la0.y + om0.y * (a[m][1] * in0));
                tile[(i1 << 8) + c] = __floats2half2_rn(la1.x + om1.x * (a[m][2] * in1),
                                                        la1.y + om1.y * (a[m][3] * in1));
            }
        }
    }
    __syncthreads();
    CBAR();   // all cluster tiles hold M

    // ---- phase 3: symmetrize + exp (DSMEM peer reads, reg-staged) ----
    {
        int i0 = (tid & 15) << 3;    // 8 rows
        int j0 = (tid >> 4) << 3;    // 8 cols (64 groups)
        uint4 pv[8];
        #pragma unroll
        for (int jj = 0; jj < 8; ++jj) {
            int j = j0 + jj;
            unsigned laddr = sbase + (unsigned)((((j & 127) << 9) + (rank << 7) + i0) << 1);
            unsigned raddr;
            asm volatile("mapa.shared::cluster.u32 %0, %1, %2;"
                         : "=r"(raddr) : "r"(laddr), "r"(j >> 7));
            asm volatile("ld.shared::cluster.v4.u32 {%0,%1,%2,%3}, [%4];"
                         : "=r"(pv[jj].x), "=r"(pv[jj].y), "=r"(pv[jj].z), "=r"(pv[jj].w)
                         : "r"(raddr));
        }
        CBAR();   // all reads done -> safe to overwrite
        #pragma unroll
        for (int ii = 0; ii < 8; ++ii) {
            int i = i0 + ii;
            __half2* rowp = &tile[(i << 8) + (j0 >> 1)];
            uint4 o0 = *(const uint4*)rowp;
            __half oh[8];
            *(uint4*)&oh[0] = o0;
            __half rh[8];
            #pragma unroll
            for (int jj = 0; jj < 8; ++jj) {
                float pe = __half2float(((const __half*)&pv[jj])[ii]);
                float ow = __half2float(oh[jj]);
                rh[jj] = __float2half_rn(__expf(0.5f * (ow + pe)));
            }
            *(uint4*)rowp = *(const uint4*)&rh[0];
        }
    }
    if (tid < 512) s_y[tid] = 1.0f;   // buffer 0 = ev_init

    // ---- hoisted V load: raw V fp16 -> Vs2 row-paired fp32 layout ----
    {
        const __half2* V16 = g_v16 + hb * 8192;
        float* Vsf = (float*)Vs2;
        for (int idx = tid; idx < 8192; idx += 1024) {
            int j = idx >> 4, c2 = idx & 15;   // row j, half2 col pair (2c2, 2c2+1)
            float2 v = __half22float2(V16[idx]);
            int cpair = j >> 1, par = j & 1;
            // Vs2[cpair][e]: component par holds row j
            Vsf[((cpair << 5) + (c2 << 1)) * 2 + par]     = v.x;
            Vsf[((cpair << 5) + (c2 << 1) + 1) * 2 + par] = v.y;
        }
    }
    __syncthreads();

    // ---- phase 4: Sinkhorn, HSTEPS_ half-steps (uint4 + HFMA2 chunks) ----
    int cur = 0;
    for (int hstep = 0; hstep < HSTEPS_; ++hstep) {
        const float* yb = &s_y[cur << 9];
        float4 ya0 = *(const float4*)&yb[lane * 8];
        float4 ya1 = *(const float4*)&yb[lane * 8 + 4];
        float4 yb0 = *(const float4*)&yb[256 + lane * 8];
        float4 yb1 = *(const float4*)&yb[256 + lane * 8 + 4];
        __half2 yh0 = __floats2half2_rn(ya0.x, ya0.y);
        __half2 yh1 = __floats2half2_rn(ya0.z, ya0.w);
        __half2 yh2 = __floats2half2_rn(ya1.x, ya1.y);
        __half2 yh3 = __floats2half2_rn(ya1.z, ya1.w);
        __half2 yh4 = __floats2half2_rn(yb0.x, yb0.y);
        __half2 yh5 = __floats2half2_rn(yb0.z, yb0.w);
        __half2 yh6 = __floats2half2_rn(yb1.x, yb1.y);
        __half2 yh7 = __floats2half2_rn(yb1.z, yb1.w);

        int nxt = cur ^ 1;
        #pragma unroll
        for (int rr = 0; rr < 4; ++rr) {
            int i = warp + rr * NW_;
            const uint4* rowq = (const uint4*)(tile + (i << 8));
            uint4 ea = rowq[lane];
            uint4 eb = rowq[lane + 32];
            __half2 a0 = __hmul2(*(const __half2*)&ea.x, yh0);
            a0 = __hfma2(*(const __half2*)&ea.y, yh1, a0);
            a0 = __hfma2(*(const __half2*)&ea.z, yh2, a0);
            a0 = __hfma2(*(const __half2*)&ea.w, yh3, a0);
            __half2 a1 = __hmul2(*(const __half2*)&eb.x, yh4);
            a1 = __hfma2(*(const __half2*)&eb.y, yh5, a1);
            a1 = __hfma2(*(const __half2*)&eb.z, yh6, a1);
            a1 = __hfma2(*(const __half2*)&eb.w, yh7, a1);
            float2 f0 = __half22float2(a0);
            float2 f1 = __half22float2(a1);
            float acc = f0.x + f0.y + f1.x + f1.y;
            #pragma unroll
            for (int o = 16; o; o >>= 1) acc += __shfl_xor_sync(0xffffffffu, acc, o);
            if (lane == 0) {
                float r = 1.0f / acc;
                if (!(hstep & 1)) s_ul[i] = r;
                unsigned laddr = sbase + (unsigned)(SM_Y + (((nxt << 9) + (rank << 7) + i) << 2));
                #pragma unroll
                for (int tr = 0; tr < 4; ++tr) {
                    unsigned raddr;
                    asm volatile("mapa.shared::cluster.u32 %0, %1, %2;"
                                 : "=r"(raddr) : "r"(laddr), "r"(tr));
                    asm volatile("st.shared::cluster.f32 [%0], %1;"
                                 :: "r"(raddr), "f"(r) : "memory");
                }
            }
        }
        CBAR();
        cur ^= 1;
    }
    // s_y[cur] = final ev (512), s_ul = final eu (local 128)

    // ---- phase 5: scale Vs2 in place by ev ----
    {
        const float* evf = &s_y[cur << 9];
        float* Vsf = (float*)Vs2;
        for (int idx = tid; idx < 16384; idx += 1024) {
            int par = idx & 1, cpair = idx >> 6;
            int j = (cpair << 1) | par;
            Vsf[idx] *= evf[j];
        }
    }
    __syncthreads();

    // ---- phase 6: out = eu * (E @ V*ev), 4 rows per warp, paired loads ----
    {
        float acc[4];
        #pragma unroll
        for (int r = 0; r < 4; ++r) acc[r] = 0.f;
        const __half2* trow = tile + ((warp << 2) << 8);
        #pragma unroll 2
        for (int c2 = 0; c2 < 256; c2 += 2) {
            float2 v0 = Vs2[(c2 << 5) + lane];
            float2 v1 = Vs2[((c2 + 1) << 5) + lane];
            #pragma unroll
            for (int r = 0; r < 4; ++r) {
                uint2 pq = *(const uint2*)&trow[(r << 8) + c2];
                float2 p0 = __half22float2(*(const __half2*)&pq.x);
                float2 p1 = __half22float2(*(const __half2*)&pq.y);
                acc[r] += p0.x * v0.x + p0.y * v0.y + p1.x * v1.x + p1.y * v1.y;
            }
        }
        int h = hb >> 4, b = hb & 15;
        #pragma unroll
        for (int r = 0; r < 4; ++r) {
            int gi = (rank << 7) + (warp << 2) + r;
            out[(((size_t)(b * T_ + gi)) << 8) + (h << 5) + lane]
                = s_ul[(warp << 2) + r] * acc[r];
        }
    }
}

// ---------------- launch ----------------
extern "C" void kernel_launch(void* const* d_in, const int* in_sizes, int n_in,
                              void* d_out, int out_size) {
    const float* X  = (const float*)d_in[0];
    const float* te = (const float*)d_in[1];
    const float* Wq = (const float*)d_in[2];
    const float* Wk = (const float*)d_in[3];
    const float* Qb = (const float*)d_in[4];
    const float* Kb = (const float*)d_in[5];
    const float* WV = (const float*)d_in[6];
    const float* A  = (const float*)d_in[7];
    const float* L  = (const float*)d_in[8];
    float* out = (float*)d_out;

    cudaFuncSetAttribute(k57, cudaFuncAttributeMaxDynamicSharedMemorySize, SMEM57);

    k1_weights<<<T_, 256>>>(te, Wq, Wk);
    kA<<<2560, 256>>>(Qb, Kb, X, WV, A, L);
    k3_qk<<<dim3(T_, 2), 256>>>(X);
    k57<<<HB_ * 4, 1024, SMEM57>>>(out);
}

// round 17
// speedup vs baseline: 1.2207x; 1.1162x over previous
#include <cuda_runtime.h>
#include <cuda_fp16.h>
#include <math.h>

#define B_ 16
#define T_ 512
#define D_ 256
#define H_ 8
#define E_ 32
#define BASIS_ 8
#define HB_ 128          // H_*B_
#define HE_ 256          // H_*E_

// ---------------- scratch (static device globals; no allocation) ----------------
__device__ float   g_qw[T_*BASIS_];
__device__ float   g_kw[T_*BASIS_];
__device__ __half2 g_Qt16[T_*D_*HE_/2];    // 67MB
__device__ __half2 g_Kt16[T_*D_*HE_/2];    // 67MB
__device__ float   g_q[HB_*T_*E_];         // [h][b][t][e] fp32
__device__ float   g_k[HB_*T_*E_];
__device__ __half2 g_v16[HB_*T_*E_/2];     // [h][b][t][e] fp16
__device__ __half2 g_lamA2[T_*256];
__device__ __half2 g_oml2[T_*256];

// ---------------- mma / ldmatrix helpers (validated R7/R9) ----------------
__device__ __forceinline__ void ldsm_x4(unsigned &r0, unsigned &r1, unsigned &r2, unsigned &r3,
                                        unsigned addr) {
    asm volatile("ldmatrix.sync.aligned.m8n8.x4.shared.b16 {%0,%1,%2,%3},[%4];"
                 : "=r"(r0), "=r"(r1), "=r"(r2), "=r"(r3) : "r"(addr));
}
__device__ __forceinline__ void ldsm_x4t(unsigned &r0, unsigned &r1, unsigned &r2, unsigned &r3,
                                         unsigned addr) {
    asm volatile("ldmatrix.sync.aligned.m8n8.x4.trans.shared.b16 {%0,%1,%2,%3},[%4];"
                 : "=r"(r0), "=r"(r1), "=r"(r2), "=r"(r3) : "r"(addr));
}
__device__ __forceinline__ void mma16816(float* d, unsigned a0, unsigned a1, unsigned a2,
                                         unsigned a3, unsigned b0, unsigned b1) {
    asm volatile("mma.sync.aligned.m16n8k16.row.col.f32.f16.f16.f32 "
                 "{%0,%1,%2,%3},{%4,%5,%6,%7},{%8,%9},{%0,%1,%2,%3};"
                 : "+f"(d[0]), "+f"(d[1]), "+f"(d[2]), "+f"(d[3])
                 : "r"(a0), "r"(a1), "r"(a2), "r"(a3), "r"(b0), "r"(b1));
}

// ---------------- K1: per-token basis mixing weights ----------------
__global__ void k1_weights(const float* __restrict__ te,
                           const float* __restrict__ Wq,
                           const float* __restrict__ Wk) {
    int t = blockIdx.x;
    int warp = threadIdx.x >> 5, lane = threadIdx.x & 31;
    const float* tr = te + t * D_;
    const float* wq = Wq + (t * BASIS_ + warp) * D_;
    const float* wk = Wk + (t * BASIS_ + warp) * D_;
    float aq = 0.f, ak = 0.f;
    #pragma unroll
    for (int m = 0; m < D_ / 32; ++m) {
        int d = lane + 32 * m;
        float x = tr[d];
        aq += x * wq[d];
        ak += x * wk[d];
    }
    #pragma unroll
    for (int o = 16; o; o >>= 1) {
        aq += __shfl_xor_sync(0xffffffffu, aq, o);
        ak += __shfl_xor_sync(0xffffffffu, ak, o);
    }
    if (lane == 0) {
        g_qw[t * BASIS_ + warp] = aq;
        g_kw[t * BASIS_ + warp] = ak;
    }
}

// ---------------- KA: merged k2_tilde + V projection + k4_mix ----------------
__global__ __launch_bounds__(256) void kA(const float* __restrict__ Qb,
                                          const float* __restrict__ Kb,
                                          const float* __restrict__ X,
                                          const float* __restrict__ WV,
                                          const float* __restrict__ A,
                                          const float* __restrict__ L) {
    __shared__ float smem[4096];
    int bid = blockIdx.x;
    int tid = threadIdx.x;

    if (bid < 1024) {
        // ---- k2_tilde ----
        float* sW = smem;
        int f4blk = bid & 63, qk = (bid >> 6) & 1, t0 = (bid >> 7) << 6;
        const float* W = (qk ? g_kw : g_qw) + t0 * BASIS_;
        const float* Bs = qk ? Kb : Qb;
        uint2* Out = qk ? (uint2*)g_Kt16 : (uint2*)g_Qt16;
        for (int idx = tid; idx < 64 * BASIS_; idx += 256) sW[idx] = W[idx];
        __syncthreads();

        int f4 = f4blk * 256 + tid;
        float4 b4[BASIS_];
        #pragma unroll
        for (int k = 0; k < BASIS_; ++k) b4[k] = ((const float4*)Bs)[k * 16384 + f4];

        for (int tt = 0; tt < 64; ++tt) {
            float4 a = make_float4(0.f, 0.f, 0.f, 0.f);
            #pragma unroll
            for (int k = 0; k < BASIS_; ++k) {
                float w = sW[tt * BASIS_ + k];
                a.x += w * b4[k].x; a.y += w * b4[k].y;
                a.z += w * b4[k].z; a.w += w * b4[k].w;
            }
            __half2 h0 = __floats2half2_rn(a.x, a.y);
            __half2 h1 = __floats2half2_rn(a.z, a.w);
            uint2 u;
            u.x = *(const unsigned int*)&h0;
            u.y = *(const unsigned int*)&h1;
            Out[(t0 + tt) * 16384 + f4] = u;
        }
    } else if (bid < 2048) {
        // ---- V projection (fp32 W -> fp16 out), column half per block ----
        float* xsT = smem;
        int t = (bid - 1024) >> 1, half = (bid - 1024) & 1;
        for (int idx = tid; idx < B_ * D_; idx += 256) {
            int b = idx >> 8, d = idx & 255;
            xsT[d * 16 + b] = X[((size_t)b * T_ + t) * D_ + d];
        }
        __syncthreads();

        int tc = tid & 31;
        int tb = tid >> 5;
        float acc[2][4];
        #pragma unroll
        for (int i = 0; i < 2; ++i)
            #pragma unroll
            for (int j = 0; j < 4; ++j) acc[i][j] = 0.f;
        int e0 = (half << 7) + (tc << 2);
        const float* W = WV + (size_t)t * 65536;
        #pragma unroll 8
        for (int d = 0; d < D_; ++d) {
            float2 xv = *(const float2*)&xsT[d * 16 + (tb << 1)];
            float4 wv = *(const float4*)&W[(d << 8) + e0];
            acc[0][0] += xv.x * wv.x; acc[0][1] += xv.x * wv.y;
            acc[0][2] += xv.x * wv.z; acc[0][3] += xv.x * wv.w;
            acc[1][0] += xv.y * wv.x; acc[1][1] += xv.y * wv.y;
            acc[1][2] += xv.y * wv.z; acc[1][3] += xv.y * wv.w;
        }
        int h = e0 >> 5, eo = e0 & 31;
        #pragma unroll
        for (int i = 0; i < 2; ++i) {
            int b = (tb << 1) + i;
            __half2 h0 = __floats2half2_rn(acc[i][0], acc[i][1]);
            __half2 h1 = __floats2half2_rn(acc[i][2], acc[i][3]);
            uint2 u;
            u.x = *(const unsigned int*)&h0;
            u.y = *(const unsigned int*)&h1;
            *(uint2*)&g_v16[(((size_t)(h * B_ + b) * T_ + t) << 4) + (eo >> 1)] = u;
        }
    } else {
        // ---- k4_mix ----
        int t = bid - 2048, c = tid;
        int j0 = c << 1, j1 = j0 + 1;
        float a0 = 0.5f * (A[t * T_ + j0] + A[j0 * T_ + t]);
        float a1 = 0.5f * (A[t * T_ + j1] + A[j1 * T_ + t]);
        float lam0 = 1.0f / (1.0f + __expf(-L[t * T_ + j0]));
        float lam1 = 1.0f / (1.0f + __expf(-L[t * T_ + j1]));
        g_lamA2[t * 256 + c] = __floats2half2_rn(lam0 * a0, lam1 * a1);
        g_oml2[t * 256 + c]  = __floats2half2_rn(1.0f - lam0, 1.0f - lam1);
    }
}

// ---------------- K3MMA: q/k projections via HMMA ----------------
// CTA per (t, side): C[16 b, 256 e] = Xt[16,256] @ Wt[256,256], fp32 accum.
// Xs: fp16 [16][264] (528B stride, conflict-free ldsm). Ws: fp16 [256][264].
#define X3_OFF 0
#define W3_OFF 8448          // 16*528
#define SMEM3  143616        // 8448 + 256*528

__global__ __launch_bounds__(256) void k3mma(const float* __restrict__ X) {
    extern __shared__ char s3[];
    __half* Xs = (__half*)(s3 + X3_OFF);
    __half* Ws = (__half*)(s3 + W3_OFF);

    int t = blockIdx.x, side = blockIdx.y;
    int tid = threadIdx.x;
    int warp = tid >> 5, lane = tid & 31;

    // stage X tile fp32 -> fp16 (16 rows x 256)
    for (int idx = tid; idx < 1024; idx += 256) {
        int b = idx >> 6, d4 = idx & 63;
        float4 xv = *(const float4*)&X[((size_t)(b * T_ + t) << 8) + (d4 << 2)];
        __half2 p0 = __floats2half2_rn(xv.x, xv.y);
        __half2 p1 = __floats2half2_rn(xv.z, xv.w);
        uint2 u;
        u.x = *(const unsigned*)&p0;
        u.y = *(const unsigned*)&p1;
        *(uint2*)&Xs[b * 264 + (d4 << 2)] = u;
    }
    // stage W-tilde fp16 (256 rows x 256 halfs = 32 uint4 per row)
    {
        const uint4* Wg = (const uint4*)((side == 0 ? g_Qt16 : g_Kt16) + (size_t)t * 32768);
        for (int idx = tid; idx < 8192; idx += 256) {
            int d = idx >> 5, c8 = idx & 31;
            *(uint4*)&Ws[d * 264 + (c8 << 3)] = Wg[idx];
        }
    }
    __syncthreads();

    unsigned sb;
    asm("{ .reg .u64 t; cvta.to.shared.u64 t, %1; cvt.u32.u64 %0, t; }" : "=r"(sb) : "l"(s3));
    // A fragment: rows = b (lane&15), 16B col chunk selected by lane>>4
    unsigned aaddr = sb + (unsigned)((lane & 15) * 528 + ((lane >> 4) << 4));
    // B fragment: rows = d (lane&15) within k-chunk, col base = warp*32 cols
    unsigned baddr = sb + W3_OFF + (unsigned)((lane & 15) * 528 + warp * 64 + ((lane >> 4) << 4));

    float d0[4] = {0,0,0,0}, d1[4] = {0,0,0,0}, d2[4] = {0,0,0,0}, d3[4] = {0,0,0,0};

    #pragma unroll 4
    for (int kt = 0; kt < 16; ++kt) {
        unsigned a0, a1, a2, a3, b0, b1, b2, b3;
        ldsm_x4(a0, a1, a2, a3, aaddr + kt * 32);
        unsigned bk = baddr + (unsigned)(kt * 8448);
        ldsm_x4t(b0, b1, b2, b3, bk);
        mma16816(d0, a0, a1, a2, a3, b0, b1);
        mma16816(d1, a0, a1, a2, a3, b2, b3);
        ldsm_x4t(b0, b1, b2, b3, bk + 32);
        mma16816(d2, a0, a1, a2, a3, b0, b1);
        mma16816(d3, a0, a1, a2, a3, b2, b3);
    }

    // epilogue (R9-validated frag mapping): rows b = lane>>2 (+8), cols e = warp*32 + f*8 + (lane&3)*2
    float* Out = (side == 0) ? g_q : g_k;
    int b_lo = lane >> 2, b_hi = b_lo + 8;
    float* frags[4] = {d0, d1, d2, d3};
    #pragma unroll
    for (int f = 0; f < 4; ++f) {
        int e = (warp << 5) + (f << 3) + ((lane & 3) << 1);
        int h = e >> 5, eo = e & 31;
        *(float2*)&Out[((size_t)((h * B_ + b_lo) * T_ + t) << 5) + eo]
            = make_float2(frags[f][0], frags[f][1]);
        *(float2*)&Out[((size_t)((h * B_ + b_hi) * T_ + t) << 5) + eo]
            = make_float2(frags[f][2], frags[f][3]);
    }
}

// ---------------- K57: fused scores+softmax+mix+symexp+Sinkhorn+PV ----------------
#define SM_UNION 131072
#define SM_Y     196864
#define SM_UL    200960
#define SMEM57   201472
#define NW_      32       // warps per CTA
#define HSTEPS_  16       // 8 Sinkhorn iterations (residual <=1.4e-5 << fp16 noise)

#define CBAR() do { \
    asm volatile("barrier.cluster.arrive.aligned;" ::: "memory"); \
    asm volatile("barrier.cluster.wait.aligned;"  ::: "memory"); } while (0)

__global__ __launch_bounds__(1024) __cluster_dims__(4, 1, 1)
void k57(float* __restrict__ out) {
    extern __shared__ char sm[];
    __half2* tile = (__half2*)sm;                 // [128][256] half2 = M/E rows fp16
    float2*  kT2  = (float2*)(sm + SM_UNION);     // [32][257] float2 (phase 1-2)
    float2*  Vs2  = (float2*)(sm + SM_UNION);     // [256][32] float2
    float*   s_y  = (float*)(sm + SM_Y);          // [2][512]
    float*   s_ul = (float*)(sm + SM_UL);         // [128]

    int tid = threadIdx.x;
    int hb = blockIdx.x >> 2;
    int rank = blockIdx.x & 3;
    int warp = tid >> 5, lane = tid & 31;

    unsigned sbase;
    asm("{ .reg .u64 t; cvta.to.shared.u64 t, %1; cvt.u32.u64 %0, t; }"
        : "=r"(sbase) : "l"(sm));

    // ---- phase 1: K transpose into kT2 ----
    const float* K = g_k + hb * (T_ * E_);
    for (int idx = tid; idx < T_ * E_; idx += 1024) {
        int t = idx >> 5, e = idx & 31;
        ((float*)&kT2[e * 257 + (t >> 1)])[t & 1] = K[idx];
    }
    __syncthreads();

    // ---- phase 2: scores + softmax + mix -> tile (fp16 M, local rows) ----
    {
        const float* Q = g_q + hb * (T_ * E_);
        const float SC = 0.17677669529663687f;
        for (int p = warp; p < 64; p += NW_) {
            int i0 = p << 1, i1 = i0 + 1;
            int gi0 = (rank << 7) + i0, gi1 = gi0 + 1;
            float q0 = Q[(gi0 << 5) + lane];
            float q1 = Q[(gi1 << 5) + lane];
            float a[8][4];
            #pragma unroll
            for (int m = 0; m < 8; ++m) { a[m][0] = a[m][1] = a[m][2] = a[m][3] = 0.f; }
            #pragma unroll
            for (int d = 0; d < 32; ++d) {
                float qd0 = __shfl_sync(0xffffffffu, q0, d);
                float qd1 = __shfl_sync(0xffffffffu, q1, d);
                const float2* row = &kT2[d * 257];
                #pragma unroll
                for (int m = 0; m < 8; ++m) {
                    float2 kv = row[lane + (m << 5)];
                    a[m][0] += qd0 * kv.x; a[m][1] += qd0 * kv.y;
                    a[m][2] += qd1 * kv.x; a[m][3] += qd1 * kv.y;
                }
            }
            float mx0 = -1e30f, mx1 = -1e30f;
            #pragma unroll
            for (int m = 0; m < 8; ++m) {
                a[m][0] *= SC; a[m][1] *= SC; a[m][2] *= SC; a[m][3] *= SC;
                mx0 = fmaxf(mx0, fmaxf(a[m][0], a[m][1]));
                mx1 = fmaxf(mx1, fmaxf(a[m][2], a[m][3]));
            }
            #pragma unroll
            for (int o = 16; o; o >>= 1) {
                mx0 = fmaxf(mx0, __shfl_xor_sync(0xffffffffu, mx0, o));
                mx1 = fmaxf(mx1, __shfl_xor_sync(0xffffffffu, mx1, o));
            }
            float sm0 = 0.f, sm1 = 0.f;
            #pragma unroll
            for (int m = 0; m < 8; ++m) {
                a[m][0] = __expf(a[m][0] - mx0); a[m][1] = __expf(a[m][1] - mx0);
                a[m][2] = __expf(a[m][2] - mx1); a[m][3] = __expf(a[m][3] - mx1);
                sm0 += a[m][0] + a[m][1];
                sm1 += a[m][2] + a[m][3];
            }
            #pragma unroll
            for (int o = 16; o; o >>= 1) {
                sm0 += __shfl_xor_sync(0xffffffffu, sm0, o);
                sm1 += __shfl_xor_sync(0xffffffffu, sm1, o);
            }
            float in0 = 1.0f / sm0, in1 = 1.0f / sm1;
            #pragma unroll
            for (int m = 0; m < 8; ++m) {
                int c = lane + (m << 5);
                float2 la0 = __half22float2(g_lamA2[gi0 * 256 + c]);
                float2 om0 = __half22float2(g_oml2[gi0 * 256 + c]);
                float2 la1 = __half22float2(g_lamA2[gi1 * 256 + c]);
                float2 om1 = __half22float2(g_oml2[gi1 * 256 + c]);
                tile[(i0 << 8) + c] = __floats2half2_rn(la0.x + om0.x * (a[m][0] * in0),
                                                        la0.y + om0.y * (a[m][1] * in0));
                tile[(i1 << 8) + c] = __floats2half2_rn(la1.x + om1.x * (a[m][2] * in1),
                                                        la1.y + om1.y * (a[m][3] * in1));
            }
        }
    }
    __syncthreads();
    CBAR();   // all cluster tiles hold M

    // ---- phase 3: symmetrize + exp (DSMEM peer reads, reg-staged) ----
    {
        int i0 = (tid & 15) << 3;
        int j0 = (tid >> 4) << 3;
        uint4 pv[8];
        #pragma unroll
        for (int jj = 0; jj < 8; ++jj) {
            int j = j0 + jj;
            unsigned laddr = sbase + (unsigned)((((j & 127) << 9) + (rank << 7) + i0) << 1);
            unsigned raddr;
            asm volatile("mapa.shared::cluster.u32 %0, %1, %2;"
                         : "=r"(raddr) : "r"(laddr), "r"(j >> 7));
            asm volatile("ld.shared::cluster.v4.u32 {%0,%1,%2,%3}, [%4];"
                         : "=r"(pv[jj].x), "=r"(pv[jj].y), "=r"(pv[jj].z), "=r"(pv[jj].w)
                         : "r"(raddr));
        }
        CBAR();
        #pragma unroll
        for (int ii = 0; ii < 8; ++ii) {
            int i = i0 + ii;
            __half2* rowp = &tile[(i << 8) + (j0 >> 1)];
            uint4 o0 = *(const uint4*)rowp;
            __half oh[8];
            *(uint4*)&oh[0] = o0;
            __half rh[8];
            #pragma unroll
            for (int jj = 0; jj < 8; ++jj) {
                float pe = __half2float(((const __half*)&pv[jj])[ii]);
                float ow = __half2float(oh[jj]);
                rh[jj] = __float2half_rn(__expf(0.5f * (ow + pe)));
            }
            *(uint4*)rowp = *(const uint4*)&rh[0];
        }
    }
    if (tid < 512) s_y[tid] = 1.0f;

    // ---- hoisted V load: raw V fp16 -> Vs2 row-paired fp32 layout ----
    {
        const __half2* V16 = g_v16 + hb * 8192;
        float* Vsf = (float*)Vs2;
        for (int idx = tid; idx < 8192; idx += 1024) {
            int j = idx >> 4, c2 = idx & 15;
            float2 v = __half22float2(V16[idx]);
            int cpair = j >> 1, par = j & 1;
            Vsf[((cpair << 5) + (c2 << 1)) * 2 + par]     = v.x;
            Vsf[((cpair << 5) + (c2 << 1) + 1) * 2 + par] = v.y;
        }
    }
    __syncthreads();

    // ---- phase 4: Sinkhorn, HSTEPS_ half-steps (uint4 + HFMA2 chunks) ----
    int cur = 0;
    for (int hstep = 0; hstep < HSTEPS_; ++hstep) {
        const float* yb = &s_y[cur << 9];
        float4 ya0 = *(const float4*)&yb[lane * 8];
        float4 ya1 = *(const float4*)&yb[lane * 8 + 4];
        float4 yb0 = *(const float4*)&yb[256 + lane * 8];
        float4 yb1 = *(const float4*)&yb[256 + lane * 8 + 4];
        __half2 yh0 = __floats2half2_rn(ya0.x, ya0.y);
        __half2 yh1 = __floats2half2_rn(ya0.z, ya0.w);
        __half2 yh2 = __floats2half2_rn(ya1.x, ya1.y);
        __half2 yh3 = __floats2half2_rn(ya1.z, ya1.w);
        __half2 yh4 = __floats2half2_rn(yb0.x, yb0.y);
        __half2 yh5 = __floats2half2_rn(yb0.z, yb0.w);
        __half2 yh6 = __floats2half2_rn(yb1.x, yb1.y);
        __half2 yh7 = __floats2half2_rn(yb1.z, yb1.w);

        int nxt = cur ^ 1;
        #pragma unroll
        for (int rr = 0; rr < 4; ++rr) {
            int i = warp + rr * NW_;
            const uint4* rowq = (const uint4*)(tile + (i << 8));
            uint4 ea = rowq[lane];
            uint4 eb = rowq[lane + 32];
            __half2 a0 = __hmul2(*(const __half2*)&ea.x, yh0);
            a0 = __hfma2(*(const __half2*)&ea.y, yh1, a0);
            a0 = __hfma2(*(const __half2*)&ea.z, yh2, a0);
            a0 = __hfma2(*(const __half2*)&ea.w, yh3, a0);
            __half2 a1 = __hmul2(*(const __half2*)&eb.x, yh4);
            a1 = __hfma2(*(const __half2*)&eb.y, yh5, a1);
            a1 = __hfma2(*(const __half2*)&eb.z, yh6, a1);
            a1 = __hfma2(*(const __half2*)&eb.w, yh7, a1);
            float2 f0 = __half22float2(a0);
            float2 f1 = __half22float2(a1);
            float acc = f0.x + f0.y + f1.x + f1.y;
            #pragma unroll
            for (int o = 16; o; o >>= 1) acc += __shfl_xor_sync(0xffffffffu, acc, o);
            if (lane == 0) {
                float r = 1.0f / acc;
                if (!(hstep & 1)) s_ul[i] = r;
                unsigned laddr = sbase + (unsigned)(SM_Y + (((nxt << 9) + (rank << 7) + i) << 2));
                #pragma unroll
                for (int tr = 0; tr < 4; ++tr) {
                    unsigned raddr;
                    asm volatile("mapa.shared::cluster.u32 %0, %1, %2;"
                                 : "=r"(raddr) : "r"(laddr), "r"(tr));
                    asm volatile("st.shared::cluster.f32 [%0], %1;"
                                 :: "r"(raddr), "f"(r) : "memory");
                }
            }
        }
        CBAR();
        cur ^= 1;
    }

    // ---- phase 5: scale Vs2 in place by ev ----
    {
        const float* evf = &s_y[cur << 9];
        float* Vsf = (float*)Vs2;
        for (int idx = tid; idx < 16384; idx += 1024) {
            int par = idx & 1, cpair = idx >> 6;
            int j = (cpair << 1) | par;
            Vsf[idx] *= evf[j];
        }
    }
    __syncthreads();

    // ---- phase 6: out = eu * (E @ V*ev), 4 rows per warp, paired loads ----
    {
        float acc[4];
        #pragma unroll
        for (int r = 0; r < 4; ++r) acc[r] = 0.f;
        const __half2* trow = tile + ((warp << 2) << 8);
        #pragma unroll 2
        for (int c2 = 0; c2 < 256; c2 += 2) {
            float2 v0 = Vs2[(c2 << 5) + lane];
            float2 v1 = Vs2[((c2 + 1) << 5) + lane];
            #pragma unroll
            for (int r = 0; r < 4; ++r) {
                uint2 pq = *(const uint2*)&trow[(r << 8) + c2];
                float2 p0 = __half22float2(*(const __half2*)&pq.x);
                float2 p1 = __half22float2(*(const __half2*)&pq.y);
                acc[r] += p0.x * v0.x + p0.y * v0.y + p1.x * v1.x + p1.y * v1.y;
            }
        }
        int h = hb >> 4, b = hb & 15;
        #pragma unroll
        for (int r = 0; r < 4; ++r) {
            int gi = (rank << 7) + (warp << 2) + r;
            out[(((size_t)(b * T_ + gi)) << 8) + (h << 5) + lane]
                = s_ul[(warp << 2) + r] * acc[r];
        }
    }
}

// ---------------- launch ----------------
extern "C" void kernel_launch(void* const* d_in, const int* in_sizes, int n_in,
                              void* d_out, int out_size) {
    const float* X  = (const float*)d_in[0];
    const float* te = (const float*)d_in[1];
    const float* Wq = (const float*)d_in[2];
    const float* Wk = (const float*)d_in[3];
    const float* Qb = (const float*)d_in[4];
    const float* Kb = (const float*)d_in[5];
    const float* WV = (const float*)d_in[6];
    const float* A  = (const float*)d_in[7];
    const float* L  = (const float*)d_in[8];
    float* out = (float*)d_out;

    cudaFuncSetAttribute(k3mma, cudaFuncAttributeMaxDynamicSharedMemorySize, SMEM3);
    cudaFuncSetAttribute(k57,   cudaFuncAttributeMaxDynamicSharedMemorySize, SMEM3 > SMEM57 ? SMEM3 : SMEM57);
    cudaFuncSetAttribute(k57,   cudaFuncAttributeMaxDynamicSharedMemorySize, SMEM57);

    k1_weights<<<T_, 256>>>(te, Wq, Wk);
    kA<<<2560, 256>>>(Qb, Kb, X, WV, A, L);
    k3mma<<<dim3(T_, 2), 256, SMEM3>>>(X);
    k57<<<HB_ * 4, 1024, SMEM57>>>(out);
}